// round 4
// baseline (speedup 1.0000x reference)
#include <cuda_runtime.h>
#include <cuda_bf16.h>
#include <math.h>

// Problem constants
#define BB 4
#define NN 2048
#define DD 1024
#define HH 16
#define DH 64
#define BH (BB*HH)          // 64
#define M_ROWS (BB*NN)      // 8192

// Scratch (static device globals — allocation-free)
__device__ float g_q[BH * NN * DH];      // [b*H+h][n][dh]
__device__ float g_k[BH * NN * DH];
__device__ float g_v[BH * NN * DH];
__device__ float g_attn[M_ROWS * DD];    // [b*N+n][D]
__device__ float g_bias[NN];             // per-key additive logit bias
__device__ float g_gate[NN];             // per-key value gate

// ---------------------------------------------------------------------------
// Prep: col_bias and gate per key position
// ---------------------------------------------------------------------------
__global__ void prep_kernel(const float* __restrict__ ctx_ppr,
                            const float* __restrict__ ctx_trust,
                            const float* __restrict__ log_ppr_alpha,
                            const float* __restrict__ trust_scale,
                            const int* __restrict__ n_ctx_p) {
    int i = blockIdx.x * blockDim.x + threadIdx.x;
    if (i >= NN) return;
    int nc = *n_ctx_p;
    float bias = 0.0f, gate = 1.0f;
    if (i < nc) {
        bias = -log_ppr_alpha[0] * logf(fmaxf(ctx_ppr[i], 1e-8f));
        gate = 1.0f / (1.0f + __expf(-trust_scale[0] * ctx_trust[i]));
    }
    g_bias[i] = bias;
    g_gate[i] = gate;
}

// ---------------------------------------------------------------------------
// Tiled SGEMM: C[M,E] = A[M,K] * W[E,K]^T + bias[E]   (NT layout)
// BM=BN=128, BK=16, TM=TN=8, 256 threads
// Epilogue variants: QKV scatter (head-major + gate) or plain store.
// ---------------------------------------------------------------------------
#define BM 128
#define BN 128
#define BK 16
#define TM 8
#define TN 8

__device__ __forceinline__ void gemm_core(const float* __restrict__ A,
                                          const float* __restrict__ W,
                                          int K,
                                          float acc[TM][TN],
                                          float As[BK][BM],
                                          float Bs[BK][BN]) {
    int tid = threadIdx.x;
    int brow = blockIdx.y * BM;
    int bcol = blockIdx.x * BN;
    int lr = tid >> 2;            // 0..63
    int lc = (tid & 3) * 4;       // 0,4,8,12
    int tm0 = (tid >> 4) * TM;
    int tn0 = (tid & 15) * TN;

    for (int k0 = 0; k0 < K; k0 += BK) {
        #pragma unroll
        for (int i = 0; i < 2; i++) {
            int m = lr + i * 64;
            float4 va = *(const float4*)&A[(size_t)(brow + m) * K + k0 + lc];
            As[lc + 0][m] = va.x; As[lc + 1][m] = va.y;
            As[lc + 2][m] = va.z; As[lc + 3][m] = va.w;
            float4 vb = *(const float4*)&W[(size_t)(bcol + m) * K + k0 + lc];
            Bs[lc + 0][m] = vb.x; Bs[lc + 1][m] = vb.y;
            Bs[lc + 2][m] = vb.z; Bs[lc + 3][m] = vb.w;
        }
        __syncthreads();
        #pragma unroll
        for (int kk = 0; kk < BK; kk++) {
            float a[TM], b[TN];
            *(float4*)&a[0] = *(float4*)&As[kk][tm0];
            *(float4*)&a[4] = *(float4*)&As[kk][tm0 + 4];
            *(float4*)&b[0] = *(float4*)&Bs[kk][tn0];
            *(float4*)&b[4] = *(float4*)&Bs[kk][tn0 + 4];
            #pragma unroll
            for (int i = 0; i < TM; i++)
                #pragma unroll
                for (int j = 0; j < TN; j++)
                    acc[i][j] = fmaf(a[i], b[j], acc[i][j]);
        }
        __syncthreads();
    }
}

// QKV GEMM: E = 3072. Scatter into g_q/g_k/g_v with head-major layout,
// gate applied to V. A block's 128-col span lies entirely in one of q/k/v.
__global__ __launch_bounds__(256, 2)
void qkv_gemm_kernel(const float* __restrict__ x,
                     const float* __restrict__ W_in,
                     const float* __restrict__ b_in) {
    __shared__ float As[BK][BM];
    __shared__ float Bs[BK][BN];
    float acc[TM][TN];
    #pragma unroll
    for (int i = 0; i < TM; i++)
        #pragma unroll
        for (int j = 0; j < TN; j++) acc[i][j] = 0.0f;

    gemm_core(x, W_in, DD, acc, As, Bs);

    int tid = threadIdx.x;
    int brow = blockIdx.y * BM;
    int bcol = blockIdx.x * BN;
    int tm0 = (tid >> 4) * TM;
    int tn0 = (tid & 15) * TN;
    int which = bcol >> 10;   // 0=q, 1=k, 2=v (uniform per block)

    #pragma unroll
    for (int i = 0; i < TM; i++) {
        int m = brow + tm0 + i;
        int b = m >> 11;          // /2048
        int n = m & (NN - 1);
        #pragma unroll
        for (int j = 0; j < TN; j++) {
            int e = bcol + tn0 + j;
            float val = acc[i][j] + b_in[e];
            int e2 = e & (DD - 1);
            int h = e2 >> 6;
            int dh = e2 & (DH - 1);
            size_t idx = ((size_t)(b * HH + h) * NN + n) * DH + dh;
            if (which == 0)      g_q[idx] = val;
            else if (which == 1) g_k[idx] = val;
            else                 g_v[idx] = val * g_gate[n];
        }
    }
}

// Output projection GEMM: out = g_attn[M,D] * W_out[D,D]^T + b_out
__global__ __launch_bounds__(256, 2)
void out_gemm_kernel(const float* __restrict__ W_out,
                     const float* __restrict__ b_out,
                     float* __restrict__ out) {
    __shared__ float As[BK][BM];
    __shared__ float Bs[BK][BN];
    float acc[TM][TN];
    #pragma unroll
    for (int i = 0; i < TM; i++)
        #pragma unroll
        for (int j = 0; j < TN; j++) acc[i][j] = 0.0f;

    gemm_core(g_attn, W_out, DD, acc, As, Bs);

    int tid = threadIdx.x;
    int brow = blockIdx.y * BM;
    int bcol = blockIdx.x * BN;
    int tm0 = (tid >> 4) * TM;
    int tn0 = (tid & 15) * TN;

    #pragma unroll
    for (int i = 0; i < TM; i++) {
        int m = brow + tm0 + i;
        #pragma unroll
        for (int j = 0; j < TN; j += 4) {
            int e = bcol + tn0 + j;
            float4 v;
            v.x = acc[i][j + 0] + b_out[e + 0];
            v.y = acc[i][j + 1] + b_out[e + 1];
            v.z = acc[i][j + 2] + b_out[e + 2];
            v.w = acc[i][j + 3] + b_out[e + 3];
            *(float4*)&out[(size_t)m * DD + e] = v;
        }
    }
}

// ---------------------------------------------------------------------------
// Attention: streaming softmax. 64 queries per block, 1 thread per query.
// K/V tiles of 64 keys staged in shared memory.
// ---------------------------------------------------------------------------
__global__ __launch_bounds__(64)
void attn_kernel() {
    __shared__ float sbuf[8192];   // 32 KB: Q (padded) then reused as K|V tiles

    int tid = threadIdx.x;            // query within tile
    int bh = blockIdx.y;              // b*H+h
    int b = bh >> 4;
    int h = bh & (HH - 1);
    int q0 = blockIdx.x * 64;

    const float* Qb = g_q + ((size_t)bh * NN + q0) * DH;

    // Stage Q tile into padded shared (stride 65 -> conflict-free row reads)
    for (int i = tid; i < 64 * 16; i += 64) {
        int row = i >> 4, c4 = (i & 15) * 4;
        float4 v = *(const float4*)&Qb[row * DH + c4];
        float* dst = &sbuf[row * 65 + c4];
        dst[0] = v.x; dst[1] = v.y; dst[2] = v.z; dst[3] = v.w;
    }
    __syncthreads();

    float q[DH];
    #pragma unroll
    for (int d = 0; d < DH; d++) q[d] = sbuf[tid * 65 + d];
    __syncthreads();   // before reusing sbuf for K/V

    float acc[DH];
    #pragma unroll
    for (int d = 0; d < DH; d++) acc[d] = 0.0f;
    float mval = -1e30f, lsum = 0.0f;

    const float scale = 0.125f;   // 1/sqrt(64)
    float* Ks = sbuf;             // 64*64
    float* Vs = sbuf + 4096;      // 64*64

    for (int kt = 0; kt < NN / 64; kt++) {
        const float* Kb = g_k + ((size_t)bh * NN + kt * 64) * DH;
        const float* Vb = g_v + ((size_t)bh * NN + kt * 64) * DH;
        for (int i = tid; i < 1024; i += 64) {
            ((float4*)Ks)[i] = ((const float4*)Kb)[i];
            ((float4*)Vs)[i] = ((const float4*)Vb)[i];
        }
        __syncthreads();

        #pragma unroll 1
        for (int key = 0; key < 64; key++) {
            const float* kr = &Ks[key * DH];
            float s = 0.0f;
            #pragma unroll
            for (int d = 0; d < DH; d++) s = fmaf(q[d], kr[d], s);
            s = fmaf(s, scale, g_bias[kt * 64 + key]);

            if (s > mval) {
                float corr = __expf(mval - s);
                mval = s;
                lsum *= corr;
                #pragma unroll
                for (int d = 0; d < DH; d++) acc[d] *= corr;
            }
            float p = __expf(s - mval);
            lsum += p;
            const float* vr = &Vs[key * DH];
            #pragma unroll
            for (int d = 0; d < DH; d++) acc[d] = fmaf(p, vr[d], acc[d]);
        }
        __syncthreads();
    }

    float inv = 1.0f / lsum;
    int n = q0 + tid;
    float* outp = &g_attn[((size_t)b * NN + n) * DD + h * DH];
    #pragma unroll
    for (int d = 0; d < DH; d += 4) {
        float4 v;
        v.x = acc[d + 0] * inv; v.y = acc[d + 1] * inv;
        v.z = acc[d + 2] * inv; v.w = acc[d + 3] * inv;
        *(float4*)&outp[d] = v;
    }
}

// ---------------------------------------------------------------------------
// Launch
// ---------------------------------------------------------------------------
extern "C" void kernel_launch(void* const* d_in, const int* in_sizes, int n_in,
                              void* d_out, int out_size) {
    const float* x           = (const float*)d_in[0];
    const int*   n_ctx       = (const int*)  d_in[1];
    const float* ctx_ppr     = (const float*)d_in[2];
    const float* ctx_trust   = (const float*)d_in[3];
    const float* W_in        = (const float*)d_in[4];
    const float* b_in        = (const float*)d_in[5];
    const float* W_out       = (const float*)d_in[6];
    const float* b_out       = (const float*)d_in[7];
    const float* log_alpha   = (const float*)d_in[8];
    const float* trust_scale = (const float*)d_in[9];
    float* out = (float*)d_out;

    prep_kernel<<<2, 1024>>>(ctx_ppr, ctx_trust, log_alpha, trust_scale, n_ctx);

    dim3 g1(3 * DD / BN, M_ROWS / BM);   // 24 x 64
    qkv_gemm_kernel<<<g1, 256>>>(x, W_in, b_in);

    dim3 ga(NN / 64, BH);                // 32 x 64
    attn_kernel<<<ga, 64>>>();

    dim3 g2(DD / BN, M_ROWS / BM);       // 8 x 64
    out_gemm_kernel<<<g2, 256>>>(W_out, b_out, out);
}

// round 9
// speedup vs baseline: 3.4934x; 3.4934x over previous
#include <cuda_runtime.h>
#include <cuda_bf16.h>
#include <math.h>
#include <stdint.h>

// Problem constants
#define BB 4
#define NN 2048
#define DD 1024
#define HH 16
#define DH 64
#define BH (BB*HH)          // 64
#define M_ROWS (BB*NN)      // 8192

// Scratch (static device globals — allocation-free)
__device__ float g_q[BH * NN * DH];      // [b*H+h][n][dh]
__device__ float g_k[BH * NN * DH];      // [b*H+h][n][dh]
__device__ float g_vT[BH * DH * NN];     // [b*H+h][dh][n]  (transposed, gated)
__device__ float g_attn[M_ROWS * DD];    // [b*N+n][D]
__device__ float g_bias[NN];             // per-key additive logit bias
__device__ float g_gate[NN];             // per-key value gate

// ---------------------------------------------------------------------------
// m16n8k16 bf16 mma (portable PTX, sm_80+; runs on tensor pipe)
// C frag: c0=(r,2q) c1=(r,2q+1) c2=(r+8,2q) c3=(r+8,2q+1), r=lane/4, q=lane%4
// A frag (row-major): RA0=(r,2q|2q+1) RA1=(r+8,..) RA2=(r,2q+8|+9) RA3=(r+8,..)
// B frag (col-major): RB0=(k=2q|2q+1, n=r) RB1=(k=2q+8|+9, n=r)
// ---------------------------------------------------------------------------
__device__ __forceinline__ void mma_bf16(float c[4],
    uint32_t a0, uint32_t a1, uint32_t a2, uint32_t a3,
    uint32_t b0, uint32_t b1)
{
    asm volatile(
        "mma.sync.aligned.m16n8k16.row.col.f32.bf16.bf16.f32 "
        "{%0,%1,%2,%3}, {%4,%5,%6,%7}, {%8,%9}, {%0,%1,%2,%3};"
        : "+f"(c[0]), "+f"(c[1]), "+f"(c[2]), "+f"(c[3])
        : "r"(a0), "r"(a1), "r"(a2), "r"(a3), "r"(b0), "r"(b1));
}

// Convert 8 consecutive fp32 -> bf16 hi/lo, store 16B each
__device__ __forceinline__ void cvt8(const float* __restrict__ src,
                                     __nv_bfloat16* dhi, __nv_bfloat16* dlo)
{
    float4 a = *(const float4*)src;
    float4 b = *(const float4*)(src + 4);
    float f[8] = {a.x, a.y, a.z, a.w, b.x, b.y, b.z, b.w};
    uint32_t h[4], l[4];
    #pragma unroll
    for (int i = 0; i < 4; i++) {
        float x = f[2*i], y = f[2*i+1];
        __nv_bfloat16 hx = __float2bfloat16_rn(x);
        __nv_bfloat16 hy = __float2bfloat16_rn(y);
        __nv_bfloat162 hp = __halves2bfloat162(hx, hy);
        h[i] = *reinterpret_cast<uint32_t*>(&hp);
        __nv_bfloat162 lp = __floats2bfloat162_rn(x - __bfloat162float(hx),
                                                  y - __bfloat162float(hy));
        l[i] = *reinterpret_cast<uint32_t*>(&lp);
    }
    *(uint4*)dhi = make_uint4(h[0], h[1], h[2], h[3]);
    *(uint4*)dlo = make_uint4(l[0], l[1], l[2], l[3]);
}

// ---------------------------------------------------------------------------
// Prep: col_bias and gate per key position
// ---------------------------------------------------------------------------
__global__ void prep_kernel(const float* __restrict__ ctx_ppr,
                            const float* __restrict__ ctx_trust,
                            const float* __restrict__ log_ppr_alpha,
                            const float* __restrict__ trust_scale,
                            const int* __restrict__ n_ctx_p) {
    int i = blockIdx.x * blockDim.x + threadIdx.x;
    if (i >= NN) return;
    int nc = *n_ctx_p;
    float bias = 0.0f, gate = 1.0f;
    if (i < nc) {
        bias = -log_ppr_alpha[0] * logf(fmaxf(ctx_ppr[i], 1e-8f));
        gate = 1.0f / (1.0f + __expf(-trust_scale[0] * ctx_trust[i]));
    }
    g_bias[i] = bias;
    g_gate[i] = gate;
}

// ---------------------------------------------------------------------------
// Split-bf16 MMA GEMM core: C[128,128] = A[128rows,K=1024] * W[128rows,K]^T
// 256 threads, 8 warps (2m x 4n), warp tile 64x32. BK=32, double-buffered.
// SMEM stage (halves): Ah[128][40] | Al | Wh | Wl   (stride 40 -> conflict-free
// frag loads: bank = r*20+q, all distinct mod 32)
// ---------------------------------------------------------------------------
#define GS 40
#define GT (128*GS)            // 5120 halves per tile
#define GSTG (4*GT)            // 20480 halves per stage
#define GEMM_SMEM (2*GSTG*2)   // 81920 bytes

__device__ __forceinline__ void gemm_stage(const float* __restrict__ Ab,
                                           const float* __restrict__ Wb,
                                           int k0, __nv_bfloat16* st, int tid)
{
    #pragma unroll
    for (int i = 0; i < 2; i++) {
        int g = tid + 256 * i;          // 0..511
        int row = g >> 2, c8 = (g & 3) * 8;
        cvt8(Ab + (size_t)row * DD + k0 + c8,
             st + row * GS + c8, st + GT + row * GS + c8);
        cvt8(Wb + (size_t)row * DD + k0 + c8,
             st + 2*GT + row * GS + c8, st + 3*GT + row * GS + c8);
    }
}

__device__ __forceinline__ void gemm_core_mma(const float* __restrict__ Ab,
                                              const float* __restrict__ Wb,
                                              __nv_bfloat16* sm,
                                              float C[4][4][4])
{
    int tid = threadIdx.x;
    int warp = tid >> 5, lane = tid & 31;
    int r = lane >> 2, q = lane & 3;
    int wm = warp >> 2, wn = warp & 3;

    #pragma unroll
    for (int mi = 0; mi < 4; mi++)
        #pragma unroll
        for (int ni = 0; ni < 4; ni++)
            #pragma unroll
            for (int e = 0; e < 4; e++) C[mi][ni][e] = 0.0f;

    gemm_stage(Ab, Wb, 0, sm, tid);
    __syncthreads();

    for (int c = 0; c < 32; c++) {
        int s = c & 1;
        if (c + 1 < 32)
            gemm_stage(Ab, Wb, (c + 1) * 32, sm + (1 - s) * GSTG, tid);

        const __nv_bfloat16* sa = sm + s * GSTG;
        const __nv_bfloat16* sw = sa + 2 * GT;
        #pragma unroll
        for (int ks = 0; ks < 2; ks++) {
            int col = ks * 16 + 2 * q;
            uint32_t ah[4][4], al[4][4];
            #pragma unroll
            for (int mi = 0; mi < 4; mi++) {
                int row0 = wm * 64 + mi * 16 + r;
                const __nv_bfloat16* ph = sa + row0 * GS + col;
                const __nv_bfloat16* pl = ph + GT;
                ah[mi][0] = *(const uint32_t*)ph;
                ah[mi][1] = *(const uint32_t*)(ph + 8 * GS);
                ah[mi][2] = *(const uint32_t*)(ph + 8);
                ah[mi][3] = *(const uint32_t*)(ph + 8 * GS + 8);
                al[mi][0] = *(const uint32_t*)pl;
                al[mi][1] = *(const uint32_t*)(pl + 8 * GS);
                al[mi][2] = *(const uint32_t*)(pl + 8);
                al[mi][3] = *(const uint32_t*)(pl + 8 * GS + 8);
            }
            #pragma unroll
            for (int ni = 0; ni < 4; ni++) {
                int n0 = wn * 32 + ni * 8 + r;
                const __nv_bfloat16* pbh = sw + n0 * GS + col;
                const __nv_bfloat16* pbl = pbh + GT;
                uint32_t bh0 = *(const uint32_t*)pbh;
                uint32_t bh1 = *(const uint32_t*)(pbh + 8);
                uint32_t bl0 = *(const uint32_t*)pbl;
                uint32_t bl1 = *(const uint32_t*)(pbl + 8);
                #pragma unroll
                for (int mi = 0; mi < 4; mi++) {
                    mma_bf16(C[mi][ni], ah[mi][0], ah[mi][1], ah[mi][2], ah[mi][3], bh0, bh1);
                    mma_bf16(C[mi][ni], ah[mi][0], ah[mi][1], ah[mi][2], ah[mi][3], bl0, bl1);
                    mma_bf16(C[mi][ni], al[mi][0], al[mi][1], al[mi][2], al[mi][3], bh0, bh1);
                }
            }
        }
        __syncthreads();
    }
}

// QKV GEMM: scatter into g_q/g_k (head-major) and g_vT (transposed, gated)
__global__ void __launch_bounds__(256, 2)
qkv_mma_kernel(const float* __restrict__ x,
               const float* __restrict__ W_in,
               const float* __restrict__ b_in) {
    extern __shared__ __nv_bfloat16 smg[];
    float C[4][4][4];
    const float* Ab = x + (size_t)blockIdx.y * 128 * DD;
    const float* Wb = W_in + (size_t)blockIdx.x * 128 * DD;
    gemm_core_mma(Ab, Wb, smg, C);

    int tid = threadIdx.x, warp = tid >> 5, lane = tid & 31;
    int r = lane >> 2, q = lane & 3;
    int wm = warp >> 2, wn = warp & 3;
    int brow = blockIdx.y * 128, bcol = blockIdx.x * 128;
    int which = bcol >> 10;     // 0=q 1=k 2=v (uniform per block)

    #pragma unroll
    for (int mi = 0; mi < 4; mi++) {
        #pragma unroll
        for (int e2 = 0; e2 < 2; e2++) {
            int grow = brow + wm * 64 + mi * 16 + r + e2 * 8;
            int b = grow >> 11, n = grow & (NN - 1);
            float gate = g_gate[n];
            #pragma unroll
            for (int ni = 0; ni < 4; ni++) {
                int gcol = bcol + wn * 32 + ni * 8 + 2 * q;
                float v0 = C[mi][ni][e2 * 2 + 0] + b_in[gcol];
                float v1 = C[mi][ni][e2 * 2 + 1] + b_in[gcol + 1];
                int e = gcol & (DD - 1);
                int h = e >> 6, dh = e & (DH - 1);
                if (which == 2) {
                    size_t base = ((size_t)(b * HH + h) * DH + dh) * NN + n;
                    g_vT[base] = v0 * gate;
                    g_vT[base + NN] = v1 * gate;
                } else {
                    float* dst = which ? g_k : g_q;
                    *(float2*)&dst[((size_t)(b * HH + h) * NN + n) * DH + dh] =
                        make_float2(v0, v1);
                }
            }
        }
    }
}

// Output projection GEMM
__global__ void __launch_bounds__(256, 2)
out_mma_kernel(const float* __restrict__ W_out,
               const float* __restrict__ b_out,
               float* __restrict__ out) {
    extern __shared__ __nv_bfloat16 smg[];
    float C[4][4][4];
    const float* Ab = g_attn + (size_t)blockIdx.y * 128 * DD;
    const float* Wb = W_out + (size_t)blockIdx.x * 128 * DD;
    gemm_core_mma(Ab, Wb, smg, C);

    int tid = threadIdx.x, warp = tid >> 5, lane = tid & 31;
    int r = lane >> 2, q = lane & 3;
    int wm = warp >> 2, wn = warp & 3;
    int brow = blockIdx.y * 128, bcol = blockIdx.x * 128;

    #pragma unroll
    for (int mi = 0; mi < 4; mi++) {
        #pragma unroll
        for (int e2 = 0; e2 < 2; e2++) {
            int grow = brow + wm * 64 + mi * 16 + r + e2 * 8;
            #pragma unroll
            for (int ni = 0; ni < 4; ni++) {
                int gcol = bcol + wn * 32 + ni * 8 + 2 * q;
                float v0 = C[mi][ni][e2 * 2 + 0] + b_out[gcol];
                float v1 = C[mi][ni][e2 * 2 + 1] + b_out[gcol + 1];
                *(float2*)&out[(size_t)grow * DD + gcol] = make_float2(v0, v1);
            }
        }
    }
}

// ---------------------------------------------------------------------------
// Flash attention with split-bf16 warp MMA.
// CTA: 128 queries x one bh head; 8 warps, warp = 16 query rows.
// 32 chunks of 64 keys, K/V^T double-buffered.
// SMEM layout (halves, row stride 72 -> frag banks r*4+q distinct):
//   QH[128][72] @0, QL @9216
//   KV stage s @18432+s*18432: KH[64][72]+0, KL+4608, VH(Vt)[64][72]+9216, VL+13824
//   bias: 2 x 64 floats @ byte 110592
// ---------------------------------------------------------------------------
#define AS 72
#define A_QL 9216
#define A_KV 18432
#define A_KVSTG 18432
#define ATTN_SMEM (110592 + 512)

__device__ __forceinline__ void attn_stage_kv(int bh, int kt, __nv_bfloat16* st,
                                              float* sbias, int tid)
{
    const float* Kg = g_k + ((size_t)bh * NN + kt * 64) * DH;
    const float* Vg = g_vT + (size_t)bh * DH * NN + kt * 64;
    #pragma unroll
    for (int i = 0; i < 2; i++) {
        int g = tid + 256 * i;          // 0..511
        int row = g >> 3, c8 = (g & 7) * 8;
        cvt8(Kg + (size_t)row * DH + c8,
             st + row * AS + c8, st + 4608 + row * AS + c8);
        cvt8(Vg + (size_t)row * NN + c8,
             st + 9216 + row * AS + c8, st + 13824 + row * AS + c8);
    }
    if (tid < 64) sbias[tid] = g_bias[kt * 64 + tid];
}

__global__ void __launch_bounds__(256, 2)
attn_mma_kernel() {
    extern __shared__ __nv_bfloat16 sma[];
    float* sbias = (float*)((char*)sma + 110592);
    int tid = threadIdx.x, warp = tid >> 5, lane = tid & 31;
    int r = lane >> 2, q = lane & 3;
    int bh = blockIdx.y;
    int q0 = blockIdx.x * 128;

    // stage Q tile (128 x 64)
    const float* Qg = g_q + ((size_t)bh * NN + q0) * DH;
    #pragma unroll
    for (int i = 0; i < 4; i++) {
        int g = tid + 256 * i;          // 0..1023
        int row = g >> 3, c8 = (g & 7) * 8;
        cvt8(Qg + (size_t)row * DH + c8,
             sma + row * AS + c8, sma + A_QL + row * AS + c8);
    }
    attn_stage_kv(bh, 0, sma + A_KV, sbias, tid);
    __syncthreads();

    float O[8][4];
    #pragma unroll
    for (int ni = 0; ni < 8; ni++)
        #pragma unroll
        for (int e = 0; e < 4; e++) O[ni][e] = 0.0f;
    float m0 = -1e30f, m1 = -1e30f, l0 = 0.0f, l1 = 0.0f;
    const float scale = 0.125f;
    int qrow = warp * 16 + r;

    for (int kt = 0; kt < 32; kt++) {
        int s = kt & 1;
        if (kt + 1 < 32)
            attn_stage_kv(bh, kt + 1, sma + A_KV + (1 - s) * A_KVSTG,
                          sbias + (1 - s) * 64, tid);

        const __nv_bfloat16* sk = sma + A_KV + s * A_KVSTG;
        const __nv_bfloat16* sv = sk + 9216;
        const float* bptr = sbias + s * 64;

        // ---- S = Q K^T (split-bf16) ----
        float S[8][4];
        #pragma unroll
        for (int ni = 0; ni < 8; ni++)
            #pragma unroll
            for (int e = 0; e < 4; e++) S[ni][e] = 0.0f;

        #pragma unroll
        for (int ks = 0; ks < 4; ks++) {
            int col = ks * 16 + 2 * q;
            const __nv_bfloat16* pq = sma + qrow * AS + col;
            const __nv_bfloat16* pql = pq + A_QL;
            uint32_t qh0 = *(const uint32_t*)pq;
            uint32_t qh1 = *(const uint32_t*)(pq + 8 * AS);
            uint32_t qh2 = *(const uint32_t*)(pq + 8);
            uint32_t qh3 = *(const uint32_t*)(pq + 8 * AS + 8);
            uint32_t ql0 = *(const uint32_t*)pql;
            uint32_t ql1 = *(const uint32_t*)(pql + 8 * AS);
            uint32_t ql2 = *(const uint32_t*)(pql + 8);
            uint32_t ql3 = *(const uint32_t*)(pql + 8 * AS + 8);
            #pragma unroll
            for (int ni = 0; ni < 8; ni++) {
                int n0 = ni * 8 + r;
                const __nv_bfloat16* pk = sk + n0 * AS + col;
                const __nv_bfloat16* pkl = pk + 4608;
                uint32_t kh0 = *(const uint32_t*)pk;
                uint32_t kh1 = *(const uint32_t*)(pk + 8);
                uint32_t kl0 = *(const uint32_t*)pkl;
                uint32_t kl1 = *(const uint32_t*)(pkl + 8);
                mma_bf16(S[ni], qh0, qh1, qh2, qh3, kh0, kh1);
                mma_bf16(S[ni], qh0, qh1, qh2, qh3, kl0, kl1);
                mma_bf16(S[ni], ql0, ql1, ql2, ql3, kh0, kh1);
            }
        }

        // ---- scale + bias, row max ----
        float rmax0 = -1e30f, rmax1 = -1e30f;
        #pragma unroll
        for (int ni = 0; ni < 8; ni++) {
            float2 bb = *(const float2*)&bptr[ni * 8 + 2 * q];
            S[ni][0] = fmaf(S[ni][0], scale, bb.x);
            S[ni][1] = fmaf(S[ni][1], scale, bb.y);
            S[ni][2] = fmaf(S[ni][2], scale, bb.x);
            S[ni][3] = fmaf(S[ni][3], scale, bb.y);
            rmax0 = fmaxf(rmax0, fmaxf(S[ni][0], S[ni][1]));
            rmax1 = fmaxf(rmax1, fmaxf(S[ni][2], S[ni][3]));
        }
        rmax0 = fmaxf(rmax0, __shfl_xor_sync(0xFFFFFFFFu, rmax0, 1));
        rmax0 = fmaxf(rmax0, __shfl_xor_sync(0xFFFFFFFFu, rmax0, 2));
        rmax1 = fmaxf(rmax1, __shfl_xor_sync(0xFFFFFFFFu, rmax1, 1));
        rmax1 = fmaxf(rmax1, __shfl_xor_sync(0xFFFFFFFFu, rmax1, 2));

        float nm0 = fmaxf(m0, rmax0), nm1 = fmaxf(m1, rmax1);
        float corr0 = __expf(m0 - nm0), corr1 = __expf(m1 - nm1);
        m0 = nm0; m1 = nm1;

        float ls0 = 0.0f, ls1 = 0.0f;
        #pragma unroll
        for (int ni = 0; ni < 8; ni++) {
            S[ni][0] = __expf(S[ni][0] - nm0);
            S[ni][1] = __expf(S[ni][1] - nm0);
            S[ni][2] = __expf(S[ni][2] - nm1);
            S[ni][3] = __expf(S[ni][3] - nm1);
            ls0 += S[ni][0] + S[ni][1];
            ls1 += S[ni][2] + S[ni][3];
        }
        ls0 += __shfl_xor_sync(0xFFFFFFFFu, ls0, 1);
        ls0 += __shfl_xor_sync(0xFFFFFFFFu, ls0, 2);
        ls1 += __shfl_xor_sync(0xFFFFFFFFu, ls1, 1);
        ls1 += __shfl_xor_sync(0xFFFFFFFFu, ls1, 2);
        l0 = l0 * corr0 + ls0;
        l1 = l1 * corr1 + ls1;

        #pragma unroll
        for (int ni = 0; ni < 8; ni++) {
            O[ni][0] *= corr0; O[ni][1] *= corr0;
            O[ni][2] *= corr1; O[ni][3] *= corr1;
        }

        // ---- O += P V (P from registers: C-frag layout == A-frag layout) ----
        #pragma unroll
        for (int kk = 0; kk < 4; kk++) {
            const float* p0 = S[2 * kk];
            const float* p1 = S[2 * kk + 1];
            uint32_t ah[4], al[4];
            {
                __nv_bfloat16 h0 = __float2bfloat16_rn(p0[0]);
                __nv_bfloat16 h1 = __float2bfloat16_rn(p0[1]);
                __nv_bfloat162 t = __halves2bfloat162(h0, h1);
                ah[0] = *reinterpret_cast<uint32_t*>(&t);
                __nv_bfloat162 u = __floats2bfloat162_rn(p0[0] - __bfloat162float(h0),
                                                         p0[1] - __bfloat162float(h1));
                al[0] = *reinterpret_cast<uint32_t*>(&u);
            }
            {
                __nv_bfloat16 h0 = __float2bfloat16_rn(p0[2]);
                __nv_bfloat16 h1 = __float2bfloat16_rn(p0[3]);
                __nv_bfloat162 t = __halves2bfloat162(h0, h1);
                ah[1] = *reinterpret_cast<uint32_t*>(&t);
                __nv_bfloat162 u = __floats2bfloat162_rn(p0[2] - __bfloat162float(h0),
                                                         p0[3] - __bfloat162float(h1));
                al[1] = *reinterpret_cast<uint32_t*>(&u);
            }
            {
                __nv_bfloat16 h0 = __float2bfloat16_rn(p1[0]);
                __nv_bfloat16 h1 = __float2bfloat16_rn(p1[1]);
                __nv_bfloat162 t = __halves2bfloat162(h0, h1);
                ah[2] = *reinterpret_cast<uint32_t*>(&t);
                __nv_bfloat162 u = __floats2bfloat162_rn(p1[0] - __bfloat162float(h0),
                                                         p1[1] - __bfloat162float(h1));
                al[2] = *reinterpret_cast<uint32_t*>(&u);
            }
            {
                __nv_bfloat16 h0 = __float2bfloat16_rn(p1[2]);
                __nv_bfloat16 h1 = __float2bfloat16_rn(p1[3]);
                __nv_bfloat162 t = __halves2bfloat162(h0, h1);
                ah[3] = *reinterpret_cast<uint32_t*>(&t);
                __nv_bfloat162 u = __floats2bfloat162_rn(p1[2] - __bfloat162float(h0),
                                                         p1[3] - __bfloat162float(h1));
                al[3] = *reinterpret_cast<uint32_t*>(&u);
            }
            int col = kk * 16 + 2 * q;
            #pragma unroll
            for (int nd = 0; nd < 8; nd++) {
                const __nv_bfloat16* pv = sv + (nd * 8 + r) * AS + col;
                uint32_t vh0 = *(const uint32_t*)pv;
                uint32_t vh1 = *(const uint32_t*)(pv + 8);
                uint32_t vl0 = *(const uint32_t*)(pv + 4608);
                uint32_t vl1 = *(const uint32_t*)(pv + 4608 + 8);
                mma_bf16(O[nd], ah[0], ah[1], ah[2], ah[3], vh0, vh1);
                mma_bf16(O[nd], ah[0], ah[1], ah[2], ah[3], vl0, vl1);
                mma_bf16(O[nd], al[0], al[1], al[2], al[3], vh0, vh1);
            }
        }
        __syncthreads();
    }

    // ---- epilogue ----
    float inv0 = 1.0f / l0, inv1 = 1.0f / l1;
    int b = bh >> 4, h = bh & (HH - 1);
    int grow = q0 + qrow;
    #pragma unroll
    for (int nd = 0; nd < 8; nd++) {
        int col = h * DH + nd * 8 + 2 * q;
        *(float2*)&g_attn[((size_t)b * NN + grow) * DD + col] =
            make_float2(O[nd][0] * inv0, O[nd][1] * inv0);
        *(float2*)&g_attn[((size_t)b * NN + grow + 8) * DD + col] =
            make_float2(O[nd][2] * inv1, O[nd][3] * inv1);
    }
}

// ---------------------------------------------------------------------------
// Launch
// ---------------------------------------------------------------------------
extern "C" void kernel_launch(void* const* d_in, const int* in_sizes, int n_in,
                              void* d_out, int out_size) {
    const float* x           = (const float*)d_in[0];
    const int*   n_ctx       = (const int*)  d_in[1];
    const float* ctx_ppr     = (const float*)d_in[2];
    const float* ctx_trust   = (const float*)d_in[3];
    const float* W_in        = (const float*)d_in[4];
    const float* b_in        = (const float*)d_in[5];
    const float* W_out       = (const float*)d_in[6];
    const float* b_out       = (const float*)d_in[7];
    const float* log_alpha   = (const float*)d_in[8];
    const float* trust_scale = (const float*)d_in[9];
    float* out = (float*)d_out;

    cudaFuncSetAttribute(qkv_mma_kernel,
        cudaFuncAttributeMaxDynamicSharedMemorySize, GEMM_SMEM);
    cudaFuncSetAttribute(out_mma_kernel,
        cudaFuncAttributeMaxDynamicSharedMemorySize, GEMM_SMEM);
    cudaFuncSetAttribute(attn_mma_kernel,
        cudaFuncAttributeMaxDynamicSharedMemorySize, ATTN_SMEM);

    prep_kernel<<<2, 1024>>>(ctx_ppr, ctx_trust, log_alpha, trust_scale, n_ctx);

    dim3 g1(3 * DD / 128, M_ROWS / 128);   // 24 x 64
    qkv_mma_kernel<<<g1, 256, GEMM_SMEM>>>(x, W_in, b_in);

    dim3 ga(NN / 128, BH);                 // 16 x 64
    attn_mma_kernel<<<ga, 256, ATTN_SMEM>>>();

    dim3 g2(DD / 128, M_ROWS / 128);       // 8 x 64
    out_mma_kernel<<<g2, 256, GEMM_SMEM>>>(W_out, b_out, out);
}